// round 6
// baseline (speedup 1.0000x reference)
#include <cuda_runtime.h>
#include <stdint.h>

// ============================================================================
// One-sweep speculative radix-select threshold kernel (v6).
//
// thresh = rank-mf (0-based) entry of the descending sort of all inputs.
// out[i] = x[i] < thresh ? 0 : x[i].
//
// Key map (order-preserving): key = u ^ (sign ? 0xFFFFFFFF : 0x80000000).
//
// pass1: read all, write out thresholded at 1.75, compact key/idx (SoA) of
// candidates (>=1.75) into per-warp slices, smem 4096-bin hist of key>>20.
// Last block decides mode and selects digit 1 (12 bits).
// resolve (ONE persistent kernel, device grid-sync): round A (bits 19:8),
// round B (bits 7:0), fixup scatter. Fallback phases for mode 1; trivial
// rewrite for mode 2.
// ============================================================================

#define NB     1024
#define NT     256
#define NWARP  (NB * NT / 32)     // 8192
#define SLICE  512u
#define FKEY   0xBFE00000u        // key(+1.75f)
#define HBINS  4096
#define RGRID  512                // resolve grid (must be <= resident capacity)

__device__ unsigned g_h[HBINS];
__device__ unsigned g_key[NWARP * SLICE];   // 16 MB
__device__ unsigned g_idx[NWARP * SLICE];   // 16 MB
__device__ unsigned g_warpcnt[NWARP];
__device__ unsigned g_ctr[8];
__device__ unsigned g_go[8];
__device__ unsigned g_nscratch;
__device__ int      g_mode;       // 0=spec, 1=fallback, 2=trivial
__device__ int      g_overflow;
__device__ unsigned g_pref;       // accumulated digit prefix (right-aligned)
__device__ unsigned g_rank;       // residual rank
__device__ unsigned g_key32;      // final exact key
__device__ float    g_thresh;

__device__ __forceinline__ unsigned fmap_u(unsigned u) {
    return u ^ ((unsigned)((int)u >> 31) | 0x80000000u);
}
__device__ __forceinline__ float finv_map(unsigned k) {
    unsigned u = (k & 0x80000000u) ? (k ^ 0x80000000u) : ~k;
    return __uint_as_float(u);
}

// Block-cooperative descending rank-select over g_h[0..nbins). 256 threads.
// Appends the selected digit to g_pref, updates g_rank, zeroes g_h.
__device__ void select_digitN(int nbins, int append_bits, int final_stage) {
    __shared__ unsigned tsum[256];
    __shared__ unsigned wsum[8];
    int per = nbins >> 8;
    unsigned s = 0;
    int base = threadIdx.x * per;
    for (int j = 0; j < per; j++) s += g_h[base + j];
    tsum[threadIdx.x] = s;
    unsigned ws = s;
    ws += __shfl_xor_sync(0xFFFFFFFFu, ws, 16);
    ws += __shfl_xor_sync(0xFFFFFFFFu, ws, 8);
    ws += __shfl_xor_sync(0xFFFFFFFFu, ws, 4);
    ws += __shfl_xor_sync(0xFFFFFFFFu, ws, 2);
    ws += __shfl_xor_sync(0xFFFFFFFFu, ws, 1);
    if ((threadIdx.x & 31) == 0) wsum[threadIdx.x >> 5] = ws;
    __syncthreads();
    if (threadIdx.x == 0) {
        unsigned r = g_rank;
        int w = 7;
        for (; w > 0; w--) { if (r < wsum[w]) break; r -= wsum[w]; }
        int t = 31;
        for (; t > 0; t--) { unsigned c = tsum[w * 32 + t]; if (r < c) break; r -= c; }
        int b = (w * 32 + t) * per;
        int j = per - 1;
        for (; j > 0; j--) { unsigned c = g_h[b + j]; if (r < c) break; r -= c; }
        unsigned d = (unsigned)(b + j);
        unsigned p = (g_pref << append_bits) | d;
        g_pref = p;
        g_rank = r;
        if (final_stage) { g_key32 = p; g_thresh = finv_map(p); }
    }
    __syncthreads();
    for (int j = threadIdx.x; j < nbins; j += 256) g_h[j] = 0;
    __syncthreads();
}

// Grid-wide barrier for the resolve kernel; last block runs select_digitN.
__device__ void resolve_sync(int ph, int nbins, int append_bits, int fin) {
    __threadfence();
    __syncthreads();
    __shared__ unsigned slast;
    if (threadIdx.x == 0)
        slast = (atomicAdd(&g_ctr[ph], 1u) == gridDim.x - 1u) ? 1u : 0u;
    __syncthreads();
    if (slast) {
        select_digitN(nbins, append_bits, fin);
        __threadfence();
        if (threadIdx.x == 0) *(volatile unsigned*)&g_go[ph] = 1u;
    } else {
        if (threadIdx.x == 0)
            while (*(volatile unsigned*)&g_go[ph] == 0u) __nanosleep(64);
        __syncthreads();
        __threadfence();
    }
    __syncthreads();
}

// ---------------------------------------------------------------------------
__global__ void k_init() {
    int i = blockIdx.x * blockDim.x + threadIdx.x;
    if (i < HBINS) g_h[i] = 0;
    if (i < 8) { g_ctr[i] = 0; g_go[i] = 0; }
    if (i == 0) {
        g_nscratch = 0; g_mode = 0; g_overflow = 0;
        g_pref = 0; g_rank = 0; g_key32 = 0; g_thresh = 0.0f;
    }
}

// ---------------------------------------------------------------------------
__global__ void __launch_bounds__(NT) k_pass1(
        const uint4* __restrict__ a0, int n0,
        const uint4* __restrict__ a1, int n1,
        const uint4* __restrict__ a2, int n2,
        uint4* __restrict__ out,
        const int* mf_ptr, int host_mf, long long ntot) {
    __shared__ unsigned shh[HBINS];
    for (int j = threadIdx.x; j < HBINS; j += NT) shh[j] = 0;
    __syncthreads();

    int tid = blockIdx.x * blockDim.x + threadIdx.x;
    int stride = gridDim.x * blockDim.x;
    unsigned lane = threadIdx.x & 31u;
    unsigned gw = (unsigned)tid >> 5;
    unsigned sbase = gw * SLICE;
    unsigned lt = (lane == 31u) ? 0x7FFFFFFFu : ((1u << lane) - 1u);
    unsigned wo = 0;
    bool ovf = false;

#define P1_BODY(ARR, N, OUTP, EO)                                             \
    for (int i = tid; ; i += stride) {                                        \
        bool valid = i < (N);                                                 \
        if (!__any_sync(0xFFFFFFFFu, valid)) break;                           \
        uint4 v = valid ? __ldcs(&(ARR)[i]) : make_uint4(0u, 0u, 0u, 0u);     \
        unsigned k0 = fmap_u(v.x), k1 = fmap_u(v.y);                          \
        unsigned k2 = fmap_u(v.z), k3 = fmap_u(v.w);                          \
        bool c0 = valid && k0 >= FKEY, c1 = valid && k1 >= FKEY;              \
        bool c2 = valid && k2 >= FKEY, c3 = valid && k3 >= FKEY;              \
        if (valid) {                                                          \
            uint4 w;                                                          \
            w.x = c0 ? v.x : 0u;  w.y = c1 ? v.y : 0u;                        \
            w.z = c2 ? v.z : 0u;  w.w = c3 ? v.w : 0u;                        \
            __stcs(&(OUTP)[i], w);                                            \
        }                                                                     \
        unsigned b0 = __ballot_sync(0xFFFFFFFFu, c0);                         \
        unsigned b1 = __ballot_sync(0xFFFFFFFFu, c1);                         \
        unsigned b2 = __ballot_sync(0xFFFFFFFFu, c2);                         \
        unsigned b3 = __ballot_sync(0xFFFFFFFFu, c3);                         \
        unsigned t0 = __popc(b0), t1 = __popc(b1);                            \
        unsigned t2 = __popc(b2), t3 = __popc(b3);                            \
        unsigned tot = t0 + t1 + t2 + t3;                                     \
        if (tot) {                                                            \
            if (wo + tot <= SLICE) {                                          \
                unsigned o = sbase + wo;                                      \
                unsigned ib = (EO) + 4u * (unsigned)i;                        \
                unsigned p;                                                   \
                if (c0) { p = o + __popc(b0 & lt);                            \
                          g_key[p] = k0; g_idx[p] = ib;                       \
                          atomicAdd(&shh[k0 >> 20], 1u); }                    \
                o += t0;                                                      \
                if (c1) { p = o + __popc(b1 & lt);                            \
                          g_key[p] = k1; g_idx[p] = ib + 1u;                  \
                          atomicAdd(&shh[k1 >> 20], 1u); }                    \
                o += t1;                                                      \
                if (c2) { p = o + __popc(b2 & lt);                            \
                          g_key[p] = k2; g_idx[p] = ib + 2u;                  \
                          atomicAdd(&shh[k2 >> 20], 1u); }                    \
                o += t2;                                                      \
                if (c3) { p = o + __popc(b3 & lt);                            \
                          g_key[p] = k3; g_idx[p] = ib + 3u;                  \
                          atomicAdd(&shh[k3 >> 20], 1u); }                    \
                wo += tot;                                                    \
            } else {                                                          \
                ovf = true;                                                   \
            }                                                                 \
        }                                                                     \
    }
    P1_BODY(a0, n0, out, 0u)
    P1_BODY(a1, n1, out + n0, 4u * (unsigned)n0)
    P1_BODY(a2, n2, out + n0 + n1, 4u * (unsigned)(n0 + n1))
#undef P1_BODY

    if (ovf) g_overflow = 1;
    if (lane == 0) {
        g_warpcnt[gw] = wo;
        atomicAdd(&g_nscratch, wo);
    }
    __syncthreads();
    for (int j = threadIdx.x; j < HBINS; j += NT)
        if (shh[j]) atomicAdd(&g_h[j], shh[j]);
    __threadfence();

    __shared__ unsigned islast;
    if (threadIdx.x == 0)
        islast = (atomicAdd(&g_ctr[0], 1u) == gridDim.x - 1u) ? 1u : 0u;
    __syncthreads();
    if (!islast) return;

    __shared__ int smode;
    if (threadIdx.x == 0) {
        long long mf = (mf_ptr != nullptr) ? (long long)(*mf_ptr)
                                           : (long long)host_mf;
        if (mf < 0) mf = 0;
        int mode;
        if (mf >= ntot)                                        mode = 2;
        else if (g_overflow || (long long)g_nscratch < mf + 1) mode = 1;
        else                                                   mode = 0;
        g_mode = mode;
        smode = mode;
        g_rank = (unsigned)mf;
        if (mode == 2) g_thresh = 0.0f;
    }
    __syncthreads();
    if (smode == 0) {
        select_digitN(HBINS, 12, 0);
    } else if (smode == 1) {
        // clear stale candidate hist for the fallback's fresh counts
        for (int j = threadIdx.x; j < HBINS; j += NT) g_h[j] = 0;
    }
}

// ---------------------------------------------------------------------------
// Persistent resolve kernel: rounds + select + fixup in one launch.
__global__ void __launch_bounds__(NT) k_resolve(
        const uint4* __restrict__ a0, int n0,
        const uint4* __restrict__ a1, int n1,
        const uint4* __restrict__ a2, int n2,
        float4* __restrict__ out) {
    __shared__ unsigned shh[HBINS];
    int mode = g_mode;
    unsigned lane = threadIdx.x & 31u;
    unsigned w = (blockIdx.x * blockDim.x + threadIdx.x) >> 5;
    unsigned nw = (gridDim.x * blockDim.x) >> 5;
    int tid = blockIdx.x * blockDim.x + threadIdx.x;
    int stride = gridDim.x * blockDim.x;

    if (mode == 0) {
        // ---- Round A: bits [19:8], prefix = key>>20 (12 bits) ----
        for (int j = threadIdx.x; j < HBINS; j += NT) shh[j] = 0;
        __syncthreads();
        {
            const unsigned pref = g_pref;
            for (unsigned s = w; s < NWARP; s += nw) {
                unsigned cnt = g_warpcnt[s];
                if (cnt > SLICE) cnt = SLICE;
                const unsigned* kp = &g_key[s * SLICE];
                for (unsigned i = lane; i < cnt; i += 32) {
                    unsigned k = kp[i];
                    if ((k >> 20) == pref)
                        atomicAdd(&shh[(k >> 8) & 4095u], 1u);
                }
            }
        }
        __syncthreads();
        for (int j = threadIdx.x; j < HBINS; j += NT)
            if (shh[j]) atomicAdd(&g_h[j], shh[j]);
        resolve_sync(1, 4096, 12, 0);

        // ---- Round B: bits [7:0], prefix = key>>8 (24 bits) ----
        for (int j = threadIdx.x; j < 256; j += NT) shh[j] = 0;
        __syncthreads();
        {
            const unsigned pref = *(volatile unsigned*)&g_pref;
            for (unsigned s = w; s < NWARP; s += nw) {
                unsigned cnt = g_warpcnt[s];
                if (cnt > SLICE) cnt = SLICE;
                const unsigned* kp = &g_key[s * SLICE];
                for (unsigned i = lane; i < cnt; i += 32) {
                    unsigned k = kp[i];
                    if ((k >> 8) == pref)
                        atomicAdd(&shh[k & 255u], 1u);
                }
            }
        }
        __syncthreads();
        for (int j = threadIdx.x; j < 256; j += NT)
            if (shh[j]) atomicAdd(&g_h[j], shh[j]);
        resolve_sync(2, 256, 8, 1);

        // ---- Fixup: zero candidates below exact key ----
        const unsigned kf = *(volatile unsigned*)&g_key32;
        float* of = (float*)out;
        for (unsigned s = w; s < NWARP; s += nw) {
            unsigned cnt = g_warpcnt[s];
            if (cnt > SLICE) cnt = SLICE;
            const unsigned* kp = &g_key[s * SLICE];
            const unsigned* ip = &g_idx[s * SLICE];
            for (unsigned i = lane; i < cnt; i += 32) {
                if (kp[i] < kf) of[ip[i]] = 0.0f;
            }
        }
        return;
    }

    if (mode == 1) {
        // ---- FB digit 1: full read, hist of key>>20 ----
        for (int j = threadIdx.x; j < HBINS; j += NT) shh[j] = 0;
        __syncthreads();
#define FB_HIST(SDP, DMASK, PREF_SH)                                          \
        {                                                                     \
            const unsigned pref = *(volatile unsigned*)&g_pref;               \
            for (int i = tid; i < n0; i += stride) {                          \
                uint4 v = __ldcs(&a0[i]);                                     \
                unsigned kk[4] = {fmap_u(v.x), fmap_u(v.y),                   \
                                  fmap_u(v.z), fmap_u(v.w)};                  \
                for (int q = 0; q < 4; q++)                                   \
                    if ((PREF_SH) < 0 || (kk[q] >> (PREF_SH)) == pref)        \
                        atomicAdd(&shh[(kk[q] >> (SDP)) & (DMASK)], 1u);      \
            }                                                                 \
            for (int i = tid; i < n1; i += stride) {                          \
                uint4 v = __ldcs(&a1[i]);                                     \
                unsigned kk[4] = {fmap_u(v.x), fmap_u(v.y),                   \
                                  fmap_u(v.z), fmap_u(v.w)};                  \
                for (int q = 0; q < 4; q++)                                   \
                    if ((PREF_SH) < 0 || (kk[q] >> (PREF_SH)) == pref)        \
                        atomicAdd(&shh[(kk[q] >> (SDP)) & (DMASK)], 1u);      \
            }                                                                 \
            for (int i = tid; i < n2; i += stride) {                          \
                uint4 v = __ldcs(&a2[i]);                                     \
                unsigned kk[4] = {fmap_u(v.x), fmap_u(v.y),                   \
                                  fmap_u(v.z), fmap_u(v.w)};                  \
                for (int q = 0; q < 4; q++)                                   \
                    if ((PREF_SH) < 0 || (kk[q] >> (PREF_SH)) == pref)        \
                        atomicAdd(&shh[(kk[q] >> (SDP)) & (DMASK)], 1u);      \
            }                                                                 \
        }
        FB_HIST(20, 4095u, -1)
        __syncthreads();
        for (int j = threadIdx.x; j < HBINS; j += NT)
            if (shh[j]) atomicAdd(&g_h[j], shh[j]);
        resolve_sync(3, 4096, 12, 0);

        for (int j = threadIdx.x; j < HBINS; j += NT) shh[j] = 0;
        __syncthreads();
        FB_HIST(8, 4095u, 20)
        __syncthreads();
        for (int j = threadIdx.x; j < HBINS; j += NT)
            if (shh[j]) atomicAdd(&g_h[j], shh[j]);
        resolve_sync(4, 4096, 12, 0);

        for (int j = threadIdx.x; j < 256; j += NT) shh[j] = 0;
        __syncthreads();
        FB_HIST(0, 255u, 8)
        __syncthreads();
        for (int j = threadIdx.x; j < 256; j += NT)
            if (shh[j]) atomicAdd(&g_h[j], shh[j]);
        resolve_sync(5, 256, 8, 1);
#undef FB_HIST
    }

    // ---- Full rewrite (mode 1 after resolve, or mode 2 with thresh=0) ----
    const float th = *(volatile float*)&g_thresh;
    const float4* f0 = (const float4*)a0;
    const float4* f1 = (const float4*)a1;
    const float4* f2 = (const float4*)a2;
    for (int i = tid; i < n0; i += stride) {
        float4 v = f0[i];
        v.x = (v.x < th) ? 0.0f : v.x;  v.y = (v.y < th) ? 0.0f : v.y;
        v.z = (v.z < th) ? 0.0f : v.z;  v.w = (v.w < th) ? 0.0f : v.w;
        out[i] = v;
    }
    float4* o1 = out + n0;
    for (int i = tid; i < n1; i += stride) {
        float4 v = f1[i];
        v.x = (v.x < th) ? 0.0f : v.x;  v.y = (v.y < th) ? 0.0f : v.y;
        v.z = (v.z < th) ? 0.0f : v.z;  v.w = (v.w < th) ? 0.0f : v.w;
        o1[i] = v;
    }
    float4* o2 = out + n0 + n1;
    for (int i = tid; i < n2; i += stride) {
        float4 v = f2[i];
        v.x = (v.x < th) ? 0.0f : v.x;  v.y = (v.y < th) ? 0.0f : v.y;
        v.z = (v.z < th) ? 0.0f : v.z;  v.w = (v.w < th) ? 0.0f : v.w;
        o2[i] = v;
    }
}

// ============================================================================
extern "C" void kernel_launch(void* const* d_in, const int* in_sizes, int n_in,
                              void* d_out, int out_size) {
    const float* e  = (const float*)d_in[0];
    const float* m  = (const float*)d_in[1];
    const float* dp = (const float*)d_in[2];
    const int* mf_ptr = (n_in >= 4) ? (const int*)d_in[3] : nullptr;
    int ne = in_sizes[0], nm = in_sizes[1], nd = in_sizes[2];
    long long ntot = (long long)ne + (long long)nm + (long long)nd;
    int ne4 = ne / 4, nm4 = nm / 4, nd4 = nd / 4;

    const uint4* u0 = (const uint4*)e;
    const uint4* u1 = (const uint4*)m;
    const uint4* u2 = (const uint4*)dp;

    k_init<<<16, 256>>>();
    k_pass1<<<NB, NT>>>(u0, ne4, u1, nm4, u2, nd4, (uint4*)d_out,
                        mf_ptr, 500000, ntot);
    k_resolve<<<RGRID, NT>>>(u0, ne4, u1, nm4, u2, nd4, (float4*)d_out);
}